// round 5
// baseline (speedup 1.0000x reference)
#include <cuda_runtime.h>
#include <math.h>

// Problem constants
#define T_TOK 8192
#define DDIM  4096
#define NEXP  64
#define TOPK  8

// Tiling
#define BM    64
#define BK    16
#define NTH   128
#define NITER (DDIM / BK)     // 256
#define HITER (NITER / 2)     // 128  (split-K = 2 boundary: k = 2048)
#define WPAD  132             // padded duplicated-W row (128 + 4 floats)

// Packed fp32x2 FMA: two independent IEEE-rn fp32 FMAs (bit-exact vs 2x fmaf)
#define FMA2(c, a, b) \
    asm("fma.rn.f32x2 %0, %1, %2, %0;" : "+l"(c) : "l"(a), "l"(b))

__device__ __forceinline__ float lo_f(unsigned long long u) {
    return __uint_as_float((unsigned)u);
}
__device__ __forceinline__ float hi_f(unsigned long long u) {
    return __uint_as_float((unsigned)(u >> 32));
}

// 16 k-steps of the 8x4 packed outer product
__device__ __forceinline__ void tile_mma(const float* __restrict__ xsb,
                                         const float* __restrict__ wsb,
                                         unsigned long long (&acc)[4][4])
{
#pragma unroll
    for (int kk = 0; kk < BK; ++kk) {
        ulonglong2 a0 = *(const ulonglong2*)(xsb + kk * BM);       // token pairs 0,1
        ulonglong2 a1 = *(const ulonglong2*)(xsb + kk * BM + 4);   // token pairs 2,3
        ulonglong2 b0 = *(const ulonglong2*)(wsb + kk * WPAD);     // dup experts 0,1
        ulonglong2 b1 = *(const ulonglong2*)(wsb + kk * WPAD + 4); // dup experts 2,3
        unsigned long long ap[4] = {a0.x, a0.y, a1.x, a1.y};
        unsigned long long bd[4] = {b0.x, b0.y, b1.x, b1.y};
#pragma unroll
        for (int ip = 0; ip < 4; ++ip)
#pragma unroll
            for (int j = 0; j < 4; ++j)
                FMA2(acc[ip][j], ap[ip], bd[j]);
    }
}

// ----------------------------------------------------------------------------
// Fused router. Logit math: two serial ascending fmaf chains over contiguous
// K halves (k<2048, k>=2048), combined lo+hi — identical rounding to the
// passing R4 kernel. Packed f32x2 FMAs (lanes independent => same bits).
// Then per-token top-8 (tie: lowest index) + softmax.
// Block: 64 tokens x 64 experts, 128 threads, 8 tok x 4 exp per thread.
// ----------------------------------------------------------------------------
__global__ __launch_bounds__(NTH)
void router_fused(const float* __restrict__ x, const float* __restrict__ w,
                  float* __restrict__ out, int half)
{
    __shared__ float Xs[2][BK][BM];     // [buf][k][token]   8 KB
    __shared__ float Ws2[2][BK][WPAD];  // [buf][k][2e dup] ~16.9 KB
    __shared__ float Ls[BM][NEXP];      // logits            16 KB

    const int tid = threadIdx.x;
    const int t0  = blockIdx.x * BM;

    const int tt = tid & 7;          // token octet  -> tokens tt*8 .. tt*8+7
    const int te = tid >> 3;         // expert quad  -> experts te*4 .. te*4+3

    unsigned long long accA[4][4] = {}, accB[4][4] = {};

    // staging assignments
    const int xrow = tid & 63;            // token row
    const int xck  = (tid >> 6) * 8;      // k offset within BK (0 or 8)
    const int wrow = tid >> 3;            // k row (0..15)
    const int wck  = (tid & 7) * 8;       // expert col (0,8,..,56)

    const float* xg = x + (size_t)(t0 + xrow) * DDIM + xck;
    const float* wg = w + (size_t)wrow * NEXP + wck;

    const float* xsb0 = &Xs[0][0][tt * 8];
    const float* xsb1 = &Xs[1][0][tt * 8];
    const float* wsb0 = &Ws2[0][0][te * 8];
    const float* wsb1 = &Ws2[1][0][te * 8];

    // ---- prime: tile 0 -> buf 0 ----
    {
        float4 A0 = *(const float4*)(xg + 0);
        float4 A1 = *(const float4*)(xg + 4);
        float4 W0 = *(const float4*)(wg + 0);
        float4 W1 = *(const float4*)(wg + 4);
        Xs[0][xck + 0][xrow] = A0.x;  Xs[0][xck + 1][xrow] = A0.y;
        Xs[0][xck + 2][xrow] = A0.z;  Xs[0][xck + 3][xrow] = A0.w;
        Xs[0][xck + 4][xrow] = A1.x;  Xs[0][xck + 5][xrow] = A1.y;
        Xs[0][xck + 6][xrow] = A1.z;  Xs[0][xck + 7][xrow] = A1.w;
        float* d = &Ws2[0][wrow][2 * wck];
        *(float4*)(d + 0)  = make_float4(W0.x, W0.x, W0.y, W0.y);
        *(float4*)(d + 4)  = make_float4(W0.z, W0.z, W0.w, W0.w);
        *(float4*)(d + 8)  = make_float4(W1.x, W1.x, W1.y, W1.y);
        *(float4*)(d + 12) = make_float4(W1.z, W1.z, W1.w, W1.w);
    }
    __syncthreads();

    for (int it = 0; it < NITER; ++it) {
        const int buf = it & 1;
        const bool pf = (it + 1 < NITER);

        float4 A0, A1, W0, W1;
        if (pf) {
            const float* xp = xg + (it + 1) * BK;
            A0 = *(const float4*)(xp + 0);
            A1 = *(const float4*)(xp + 4);
            const float* wp = wg + (size_t)(it + 1) * BK * NEXP;
            W0 = *(const float4*)(wp + 0);
            W1 = *(const float4*)(wp + 4);
        }

        if (it < HITER)
            tile_mma(buf ? xsb1 : xsb0, buf ? wsb1 : wsb0, accA);
        else
            tile_mma(buf ? xsb1 : xsb0, buf ? wsb1 : wsb0, accB);

        if (pf) {
            const int nb = buf ^ 1;
            Xs[nb][xck + 0][xrow] = A0.x;  Xs[nb][xck + 1][xrow] = A0.y;
            Xs[nb][xck + 2][xrow] = A0.z;  Xs[nb][xck + 3][xrow] = A0.w;
            Xs[nb][xck + 4][xrow] = A1.x;  Xs[nb][xck + 5][xrow] = A1.y;
            Xs[nb][xck + 6][xrow] = A1.z;  Xs[nb][xck + 7][xrow] = A1.w;
            float* d = &Ws2[nb][wrow][2 * wck];
            *(float4*)(d + 0)  = make_float4(W0.x, W0.x, W0.y, W0.y);
            *(float4*)(d + 4)  = make_float4(W0.z, W0.z, W0.w, W0.w);
            *(float4*)(d + 8)  = make_float4(W1.x, W1.x, W1.y, W1.y);
            *(float4*)(d + 12) = make_float4(W1.z, W1.z, W1.w, W1.w);
        }
        __syncthreads();
    }

    // combine halves (ascending slice order, scalar rn adds) -> logits
#pragma unroll
    for (int ip = 0; ip < 4; ++ip)
#pragma unroll
        for (int j = 0; j < 4; ++j) {
            const int e = te * 4 + j;
            Ls[tt * 8 + 2 * ip + 0][e] = lo_f(accA[ip][j]) + lo_f(accB[ip][j]);
            Ls[tt * 8 + 2 * ip + 1][e] = hi_f(accA[ip][j]) + hi_f(accB[ip][j]);
        }
    __syncthreads();

    // ---- top-8 + softmax: 4 warps, 16 tokens each ----
    const int warp = tid >> 5;
    const int lane = tid & 31;

    for (int tk = 0; tk < 16; ++tk) {
        const int tok = warp * 16 + tk;
        float v0 = Ls[tok][lane];
        float v1 = Ls[tok][lane + 32];

        float topv[TOPK];
        int   topi[TOPK];
#pragma unroll
        for (int j = 0; j < TOPK; j++) {
            float bv; int bi;
            if (v0 >= v1) { bv = v0; bi = lane; }
            else          { bv = v1; bi = lane + 32; }
#pragma unroll
            for (int off = 16; off; off >>= 1) {
                float ov = __shfl_xor_sync(0xffffffffu, bv, off);
                int   oi = __shfl_xor_sync(0xffffffffu, bi, off);
                if (ov > bv || (ov == bv && oi < bi)) { bv = ov; bi = oi; }
            }
            topv[j] = bv;
            topi[j] = bi;
            if (bi == lane)           v0 = -INFINITY;
            else if (bi == lane + 32) v1 = -INFINITY;
        }

        const float mx = topv[0];
        float e[TOPK];
        float sum = 0.0f;
#pragma unroll
        for (int j = 0; j < TOPK; j++) { e[j] = expf(topv[j] - mx); sum += e[j]; }
        const float inv = 1.0f / sum;

        if (lane < TOPK) {
            const size_t g = (size_t)(t0 + tok) * TOPK + lane;
            out[g]        = e[lane] * inv;
            out[half + g] = (float)topi[lane];
        }
    }
}

// ----------------------------------------------------------------------------
extern "C" void kernel_launch(void* const* d_in, const int* in_sizes, int n_in,
                              void* d_out, int out_size)
{
    const float* x = (const float*)d_in[0];
    const float* w = (const float*)d_in[1];
    float* out = (float*)d_out;
    const int half = out_size >> 1;

    router_fused<<<T_TOK / BM, NTH>>>(x, w, out, half);
}

// round 9
// speedup vs baseline: 1.1716x; 1.1716x over previous
#include <cuda_runtime.h>
#include <math.h>

// Problem constants
#define T_TOK 8192
#define DDIM  4096
#define NEXP  64
#define TOPK  8

// Tiling
#define BM    64
#define BK    32
#define NTH   256
#define NITER (DDIM / BK)     // 128
#define HITER (NITER / 2)     // 64  (split-K = 2 boundary: k = 2048)
#define WDUP  128             // duplicated-W row: 64 experts x 2

// Packed fp32x2 FMA: two independent IEEE-rn fp32 FMAs (bit-exact vs 2x fmaf)
#define FMA2(c, a, b) \
    asm("fma.rn.f32x2 %0, %1, %2, %0;" : "+l"(c) : "l"(a), "l"(b))

__device__ __forceinline__ float lo_f(unsigned long long u) {
    return __uint_as_float((unsigned)u);
}
__device__ __forceinline__ float hi_f(unsigned long long u) {
    return __uint_as_float((unsigned)(u >> 32));
}

// ----------------------------------------------------------------------------
// Fused router. Logit math: two serial ascending fmaf chains over contiguous
// K halves (k<2048, k>=2048), combined lo+hi — identical rounding to the
// R4 passing kernel (packed lanes are independent => same bits).
// Block: 64 tokens x 64 experts, 256 threads, 4 tok x 4 exp per thread.
// BK=32: one barrier per 32 k-steps. Ls aliases the GEMM buffers (union) to
// fit the 48 KB static smem limit.
// ----------------------------------------------------------------------------
__global__ __launch_bounds__(NTH)
void router_fused(const float* __restrict__ x, const float* __restrict__ w,
                  float* __restrict__ out, int half)
{
    __shared__ union SmemU {
        struct {
            float Xs[2][BK][BM];     // [buf][k][token]    16 KB
            float Ws2[2][BK][WDUP];  // [buf][k][dup exp]  32 KB
        } g;                          // mainloop view: 48 KB total
        float Ls[BM][NEXP];           // epilogue view: 16 KB (aliases Xs+Ws2)
    } smem;

    float (*Xs)[BK][BM]   = smem.g.Xs;
    float (*Ws2)[BK][WDUP] = smem.g.Ws2;

    const int tid = threadIdx.x;
    const int t0  = blockIdx.x * BM;

    const int tt = tid & 15;         // token quad  -> tokens tt*4 .. tt*4+3
    const int te = tid >> 4;         // expert quad -> experts te*4 .. te*4+3

    unsigned long long accA[2][4] = {}, accB[2][4] = {};

    // staging assignments (8 floats per thread for X and for W)
    const int xrow = tid & 63;            // token row (0..63)
    const int xck  = (tid >> 6) * 8;      // k offset within BK (0,8,16,24)
    const int wrow = tid >> 3;            // k row (0..31)
    const int wck  = (tid & 7) * 8;       // expert col (0,8,..,56)

    const float* xg = x + (size_t)(t0 + xrow) * DDIM + xck;
    const float* wg = w + (size_t)wrow * NEXP + wck;

    // ---- prime: tile 0 -> buf 0 ----
    {
        float4 A0 = *(const float4*)(xg + 0);
        float4 A1 = *(const float4*)(xg + 4);
        float4 W0 = *(const float4*)(wg + 0);
        float4 W1 = *(const float4*)(wg + 4);
        Xs[0][xck + 0][xrow] = A0.x;  Xs[0][xck + 1][xrow] = A0.y;
        Xs[0][xck + 2][xrow] = A0.z;  Xs[0][xck + 3][xrow] = A0.w;
        Xs[0][xck + 4][xrow] = A1.x;  Xs[0][xck + 5][xrow] = A1.y;
        Xs[0][xck + 6][xrow] = A1.z;  Xs[0][xck + 7][xrow] = A1.w;
        float* d = &Ws2[0][wrow][wck * 2];
        *(float4*)(d + 0)  = make_float4(W0.x, W0.x, W0.y, W0.y);
        *(float4*)(d + 4)  = make_float4(W0.z, W0.z, W0.w, W0.w);
        *(float4*)(d + 8)  = make_float4(W1.x, W1.x, W1.y, W1.y);
        *(float4*)(d + 12) = make_float4(W1.z, W1.z, W1.w, W1.w);
    }
    __syncthreads();

    for (int it = 0; it < NITER; ++it) {
        const int buf = it & 1;
        const bool pf = (it + 1 < NITER);

        float4 A0, A1, W0, W1;
        if (pf) {
            const float* xp = xg + (it + 1) * BK;
            A0 = *(const float4*)(xp + 0);
            A1 = *(const float4*)(xp + 4);
            const float* wp = wg + (size_t)(it + 1) * BK * NEXP;
            W0 = *(const float4*)(wp + 0);
            W1 = *(const float4*)(wp + 4);
        }

        const float* xsb = &Xs[buf][0][tt * 4];
        const float* wsb = &Ws2[buf][0][te * 8];

        if (it < HITER) {
#pragma unroll
            for (int kk = 0; kk < BK; ++kk) {
                ulonglong2 a  = *(const ulonglong2*)(xsb + kk * BM);
                ulonglong2 b0 = *(const ulonglong2*)(wsb + kk * WDUP);
                ulonglong2 b1 = *(const ulonglong2*)(wsb + kk * WDUP + 4);
                FMA2(accA[0][0], a.x, b0.x); FMA2(accA[0][1], a.x, b0.y);
                FMA2(accA[0][2], a.x, b1.x); FMA2(accA[0][3], a.x, b1.y);
                FMA2(accA[1][0], a.y, b0.x); FMA2(accA[1][1], a.y, b0.y);
                FMA2(accA[1][2], a.y, b1.x); FMA2(accA[1][3], a.y, b1.y);
            }
        } else {
#pragma unroll
            for (int kk = 0; kk < BK; ++kk) {
                ulonglong2 a  = *(const ulonglong2*)(xsb + kk * BM);
                ulonglong2 b0 = *(const ulonglong2*)(wsb + kk * WDUP);
                ulonglong2 b1 = *(const ulonglong2*)(wsb + kk * WDUP + 4);
                FMA2(accB[0][0], a.x, b0.x); FMA2(accB[0][1], a.x, b0.y);
                FMA2(accB[0][2], a.x, b1.x); FMA2(accB[0][3], a.x, b1.y);
                FMA2(accB[1][0], a.y, b0.x); FMA2(accB[1][1], a.y, b0.y);
                FMA2(accB[1][2], a.y, b1.x); FMA2(accB[1][3], a.y, b1.y);
            }
        }

        if (pf) {
            const int nb = buf ^ 1;
            Xs[nb][xck + 0][xrow] = A0.x;  Xs[nb][xck + 1][xrow] = A0.y;
            Xs[nb][xck + 2][xrow] = A0.z;  Xs[nb][xck + 3][xrow] = A0.w;
            Xs[nb][xck + 4][xrow] = A1.x;  Xs[nb][xck + 5][xrow] = A1.y;
            Xs[nb][xck + 6][xrow] = A1.z;  Xs[nb][xck + 7][xrow] = A1.w;
            float* d = &Ws2[nb][wrow][wck * 2];
            *(float4*)(d + 0)  = make_float4(W0.x, W0.x, W0.y, W0.y);
            *(float4*)(d + 4)  = make_float4(W0.z, W0.z, W0.w, W0.w);
            *(float4*)(d + 8)  = make_float4(W1.x, W1.x, W1.y, W1.y);
            *(float4*)(d + 12) = make_float4(W1.z, W1.z, W1.w, W1.w);
        }
        __syncthreads();
    }

    // combine halves (ascending slice order, scalar rn adds) -> logits
    // (Ls aliases the now-dead GEMM buffers; accumulators live in registers)
#pragma unroll
    for (int p = 0; p < 2; ++p)
#pragma unroll
        for (int j = 0; j < 4; ++j) {
            const int e = te * 4 + j;
            smem.Ls[tt * 4 + 2 * p + 0][e] = lo_f(accA[p][j]) + lo_f(accB[p][j]);
            smem.Ls[tt * 4 + 2 * p + 1][e] = hi_f(accA[p][j]) + hi_f(accB[p][j]);
        }
    __syncthreads();

    // ---- top-8 + softmax: 8 warps, 8 tokens each ----
    const int warp = tid >> 5;
    const int lane = tid & 31;

    for (int tk = 0; tk < 8; ++tk) {
        const int tok = warp * 8 + tk;
        float v0 = smem.Ls[tok][lane];
        float v1 = smem.Ls[tok][lane + 32];

        float topv[TOPK];
        int   topi[TOPK];
#pragma unroll
        for (int j = 0; j < TOPK; j++) {
            float bv; int bi;
            if (v0 >= v1) { bv = v0; bi = lane; }
            else          { bv = v1; bi = lane + 32; }
#pragma unroll
            for (int off = 16; off; off >>= 1) {
                float ov = __shfl_xor_sync(0xffffffffu, bv, off);
                int   oi = __shfl_xor_sync(0xffffffffu, bi, off);
                if (ov > bv || (ov == bv && oi < bi)) { bv = ov; bi = oi; }
            }
            topv[j] = bv;
            topi[j] = bi;
            if (bi == lane)           v0 = -INFINITY;
            else if (bi == lane + 32) v1 = -INFINITY;
        }

        const float mx = topv[0];
        float e[TOPK];
        float sum = 0.0f;
#pragma unroll
        for (int j = 0; j < TOPK; j++) { e[j] = expf(topv[j] - mx); sum += e[j]; }
        const float inv = 1.0f / sum;

        if (lane < TOPK) {
            const size_t g = (size_t)(t0 + tok) * TOPK + lane;
            out[g]        = e[lane] * inv;
            out[half + g] = (float)topi[lane];
        }
    }
}

// ----------------------------------------------------------------------------
extern "C" void kernel_launch(void* const* d_in, const int* in_sizes, int n_in,
                              void* d_out, int out_size)
{
    const float* x = (const float*)d_in[0];
    const float* w = (const float*)d_in[1];
    float* out = (float*)d_out;
    const int half = out_size >> 1;

    router_fused<<<T_TOK / BM, NTH>>>(x, w, out, half);
}

// round 10
// speedup vs baseline: 1.9188x; 1.6378x over previous
#include <cuda_runtime.h>
#include <math.h>

// Problem constants
#define T_TOK 8192
#define DDIM  4096
#define NEXP  64
#define TOPK  8

// GEMM tiling
#define BM    64
#define BK    16
#define NTH   256
#define KHALF (DDIM / 2)       // 2048 (split-K = 2, contiguous halves)
#define NITER (KHALF / BK)     // 128

// Packed fp32x2 FMA: two independent IEEE-rn fp32 FMAs (bit-exact vs 2x fmaf)
#define FMA2(c, a, b) \
    asm("fma.rn.f32x2 %0, %1, %2, %0;" : "+l"(c) : "l"(a), "l"(b))

__device__ __forceinline__ float lo_f(unsigned long long u) {
    return __uint_as_float((unsigned)u);
}
__device__ __forceinline__ float hi_f(unsigned long long u) {
    return __uint_as_float((unsigned)(u >> 32));
}
// duplicate a scalar into both f32x2 lanes (1 MOV)
__device__ __forceinline__ unsigned long long dup2(float f) {
    unsigned u = __float_as_uint(f);
    return ((unsigned long long)u << 32) | (unsigned long long)u;
}

// Scratch: partial logits [2][T_TOK][NEXP] (4 MB)
__device__ float g_part[2][T_TOK][NEXP];

// ----------------------------------------------------------------------------
// Kernel 1: split-K=2 fp32 GEMM. blockIdx.y = K-half. Each logit half is ONE
// serial ascending fmaf chain (packed f32x2 lanes are independent tokens).
// Block: 64 tokens x 64 experts, 256 threads, 4 tok x 4 exp per thread.
// ----------------------------------------------------------------------------
__global__ __launch_bounds__(NTH)
void router_gemm(const float* __restrict__ x, const float* __restrict__ w)
{
    __shared__ __align__(16) float Xs[2][BK][BM];    // [buf][k][token]  8 KB
    __shared__ __align__(16) float Ws[2][BK][NEXP];  // [buf][k][expert] 8 KB

    const int tid = threadIdx.x;
    const int t0  = blockIdx.x * BM;
    const int k0  = blockIdx.y * KHALF;

    const int tt = tid & 15;         // token quad  -> tokens tt*4 .. tt*4+3
    const int te = tid >> 4;         // expert quad -> experts te*4 .. te*4+3

    unsigned long long acc[2][4] = {};   // [token pair][expert]

    // staging assignments (one float4 each for X and W per thread)
    const int xrow = tid >> 2;            // token row (0..63)
    const int xck  = (tid & 3) * 4;       // k offset within BK (0,4,8,12)
    const int wrow = tid >> 4;            // k row (0..15)
    const int wck  = (tid & 15) * 4;      // expert col (0,4,..,60)

    const float* xg = x + (size_t)(t0 + xrow) * DDIM + k0 + xck;
    const float* wg = w + (size_t)(k0 + wrow) * NEXP + wck;

    // ---- prime: tile 0 -> buf 0 ----
    {
        float4 A = *(const float4*)xg;
        float4 W = *(const float4*)wg;
        Xs[0][xck + 0][xrow] = A.x;
        Xs[0][xck + 1][xrow] = A.y;
        Xs[0][xck + 2][xrow] = A.z;
        Xs[0][xck + 3][xrow] = A.w;
        *(float4*)&Ws[0][wrow][wck] = W;
    }
    __syncthreads();

    for (int it = 0; it < NITER; ++it) {
        const int buf = it & 1;
        const bool pf = (it + 1 < NITER);

        float4 A, W;
        if (pf) {
            A = *(const float4*)(xg + (it + 1) * BK);
            W = *(const float4*)(wg + (size_t)(it + 1) * BK * NEXP);
        }

        const float* xsb = &Xs[buf][0][tt * 4];
        const float* wsb = &Ws[buf][0][te * 4];

#pragma unroll
        for (int kk = 0; kk < BK; ++kk) {
            ulonglong2 a = *(const ulonglong2*)(xsb + kk * BM);   // token pairs
            float4     b = *(const float4*)(wsb + kk * NEXP);     // 4 experts
            unsigned long long b0 = dup2(b.x);
            unsigned long long b1 = dup2(b.y);
            unsigned long long b2 = dup2(b.z);
            unsigned long long b3 = dup2(b.w);
            FMA2(acc[0][0], a.x, b0); FMA2(acc[0][1], a.x, b1);
            FMA2(acc[0][2], a.x, b2); FMA2(acc[0][3], a.x, b3);
            FMA2(acc[1][0], a.y, b0); FMA2(acc[1][1], a.y, b1);
            FMA2(acc[1][2], a.y, b2); FMA2(acc[1][3], a.y, b3);
        }

        if (pf) {
            const int nb = buf ^ 1;
            Xs[nb][xck + 0][xrow] = A.x;
            Xs[nb][xck + 1][xrow] = A.y;
            Xs[nb][xck + 2][xrow] = A.z;
            Xs[nb][xck + 3][xrow] = A.w;
            *(float4*)&Ws[nb][wrow][wck] = W;
        }
        __syncthreads();
    }

    // write partials for this K-half
    float* op = &g_part[blockIdx.y][t0][0];
#pragma unroll
    for (int p = 0; p < 2; ++p) {
        const int r0 = tt * 4 + 2 * p;
        *(float4*)(op + (size_t)r0 * NEXP + te * 4) =
            make_float4(lo_f(acc[p][0]), lo_f(acc[p][1]),
                        lo_f(acc[p][2]), lo_f(acc[p][3]));
        *(float4*)(op + (size_t)(r0 + 1) * NEXP + te * 4) =
            make_float4(hi_f(acc[p][0]), hi_f(acc[p][1]),
                        hi_f(acc[p][2]), hi_f(acc[p][3]));
    }
}

// ----------------------------------------------------------------------------
// Kernel 2: one warp per token. logit = half0 + half1 (ascending slice order,
// scalar rn add -> identical rounding to the R4 passing kernel), then top-8
// (tie: lowest index, matching jax.lax.top_k) + softmax.
// ----------------------------------------------------------------------------
__global__ __launch_bounds__(256)
void router_topk(float* __restrict__ out, int half)
{
    const int warp = (int)((blockIdx.x * blockDim.x + threadIdx.x) >> 5);
    const int lane = threadIdx.x & 31;
    if (warp >= T_TOK) return;

    float v0 = g_part[0][warp][lane]      + g_part[1][warp][lane];
    float v1 = g_part[0][warp][lane + 32] + g_part[1][warp][lane + 32];

    float topv[TOPK];
    int   topi[TOPK];
#pragma unroll
    for (int j = 0; j < TOPK; j++) {
        float bv; int bi;
        if (v0 >= v1) { bv = v0; bi = lane; }
        else          { bv = v1; bi = lane + 32; }
#pragma unroll
        for (int off = 16; off; off >>= 1) {
            float ov = __shfl_xor_sync(0xffffffffu, bv, off);
            int   oi = __shfl_xor_sync(0xffffffffu, bi, off);
            if (ov > bv || (ov == bv && oi < bi)) { bv = ov; bi = oi; }
        }
        topv[j] = bv;
        topi[j] = bi;
        if (bi == lane)           v0 = -INFINITY;
        else if (bi == lane + 32) v1 = -INFINITY;
    }

    const float mx = topv[0];
    float e[TOPK];
    float sum = 0.0f;
#pragma unroll
    for (int j = 0; j < TOPK; j++) { e[j] = expf(topv[j] - mx); sum += e[j]; }
    const float inv = 1.0f / sum;

    if (lane < TOPK) {
        const size_t g = (size_t)warp * TOPK + lane;
        out[g]        = e[lane] * inv;
        out[half + g] = (float)topi[lane];
    }
}

// ----------------------------------------------------------------------------
extern "C" void kernel_launch(void* const* d_in, const int* in_sizes, int n_in,
                              void* d_out, int out_size)
{
    const float* x = (const float*)d_in[0];
    const float* w = (const float*)d_in[1];
    float* out = (float*)d_out;
    const int half = out_size >> 1;

    dim3 grid1(T_TOK / BM, 2);
    router_gemm<<<grid1, NTH>>>(x, w);

    router_topk<<<T_TOK / 8, 256>>>(out, half);
}